// round 1
// baseline (speedup 1.0000x reference)
#include <cuda_runtime.h>
#include <cstdint>

// 8-bit ripple-carry adder on {0,1}-valued floats.
// A, B: [N, 8] f32 (MSB first), Cin: [N, 1] f32.
// Output layout (harness flattens & concatenates the tuple):
//   d_out[0 .. 8N)   = sums, row-major [N, 8]
//   d_out[8N .. 9N)  = carry out, [N]
//
// Pure HBM-streaming kernel: 544 MB read + 288 MB write.
// One thread per row: 4x float4 loads + 1 scalar, 2x float4 + 1 scalar stores.

__device__ __forceinline__ void full_adder(float a, float b, float c,
                                           float& s, float& cout) {
    float x = fmaf(-2.0f * a, b, a + b);   // a xor b  (exact on {0,1})
    s       = fmaf(-2.0f * x, c, x + c);   // x xor c
    cout    = fmaf(a, b, c * x);           // ab + c*(a^b)
}

__global__ void __launch_bounds__(256, 8)
adder8_kernel(const float4* __restrict__ A4,
              const float4* __restrict__ B4,
              const float* __restrict__ Cin,
              float4* __restrict__ S4,
              float* __restrict__ Cout,
              int N) {
    int row = blockIdx.x * blockDim.x + threadIdx.x;
    if (row >= N) return;

    // Row = 8 floats = 2 float4. Consecutive threads -> contiguous 32B -> coalesced.
    float4 a_lo = A4[row * 2 + 0];   // bits 0..3 (MSB side)
    float4 a_hi = A4[row * 2 + 1];   // bits 4..7 (LSB side)
    float4 b_lo = B4[row * 2 + 0];
    float4 b_hi = B4[row * 2 + 1];
    float  c    = Cin[row];

    float a[8] = {a_lo.x, a_lo.y, a_lo.z, a_lo.w, a_hi.x, a_hi.y, a_hi.z, a_hi.w};
    float b[8] = {b_lo.x, b_lo.y, b_lo.z, b_lo.w, b_hi.x, b_hi.y, b_hi.z, b_hi.w};
    float s[8];

    // Ripple from bit 7 (LSB) down to bit 0 (MSB).
    #pragma unroll
    for (int i = 7; i >= 0; --i) {
        full_adder(a[i], b[i], c, s[i], c);
    }

    float4 s_lo = make_float4(s[0], s[1], s[2], s[3]);
    float4 s_hi = make_float4(s[4], s[5], s[6], s[7]);
    S4[row * 2 + 0] = s_lo;
    S4[row * 2 + 1] = s_hi;
    Cout[row] = c;
}

extern "C" void kernel_launch(void* const* d_in, const int* in_sizes, int n_in,
                              void* d_out, int out_size) {
    const float* A   = (const float*)d_in[0];
    const float* B   = (const float*)d_in[1];
    const float* Cin = (const float*)d_in[2];

    int N = in_sizes[0] / 8;   // A has N*8 elements

    float* out   = (float*)d_out;
    float* cout_ = out + (size_t)N * 8;

    int threads = 256;
    int blocks  = (N + threads - 1) / threads;
    adder8_kernel<<<blocks, threads>>>((const float4*)A, (const float4*)B, Cin,
                                       (float4*)out, cout_, N);
}

// round 2
// speedup vs baseline: 1.0053x; 1.0053x over previous
#include <cuda_runtime.h>
#include <cstdint>

// 8-bit ripple-carry adder on {0,1}-valued floats.
// A, B: [N, 8] f32 (MSB first), Cin: [N, 1] f32.
// Output: d_out[0..8N) = sums [N,8], d_out[8N..9N) = carry [N].
//
// HBM-streaming kernel: 544 MB read + 288 MB write (~832 MB total).
// R2: 2 rows per thread (9 front-batched independent loads -> deeper MLP),
//     streaming cache hints (__ldcs/__stcs) since every byte is touched once.

__device__ __forceinline__ void full_adder(float a, float b, float c,
                                           float& s, float& cout) {
    float x = fmaf(-2.0f * a, b, a + b);   // a xor b  (exact on {0,1})
    s       = fmaf(-2.0f * x, c, x + c);   // x xor c
    cout    = fmaf(a, b, c * x);           // ab + c*(a^b)
}

__device__ __forceinline__ void ripple8(const float4& alo, const float4& ahi,
                                        const float4& blo, const float4& bhi,
                                        float c, float4& slo, float4& shi,
                                        float& cout) {
    float a[8] = {alo.x, alo.y, alo.z, alo.w, ahi.x, ahi.y, ahi.z, ahi.w};
    float b[8] = {blo.x, blo.y, blo.z, blo.w, bhi.x, bhi.y, bhi.z, bhi.w};
    float s[8];
    #pragma unroll
    for (int i = 7; i >= 0; --i) {
        full_adder(a[i], b[i], c, s[i], c);
    }
    slo = make_float4(s[0], s[1], s[2], s[3]);
    shi = make_float4(s[4], s[5], s[6], s[7]);
    cout = c;
}

__global__ void __launch_bounds__(256, 4)
adder8_kernel(const float4* __restrict__ A4,
              const float4* __restrict__ B4,
              const float2* __restrict__ Cin2,
              float4* __restrict__ S4,
              float2* __restrict__ Cout2,
              int Npairs) {
    int p = blockIdx.x * blockDim.x + threadIdx.x;   // pair index (2 rows)
    if (p >= Npairs) return;

    // Front-batch all 9 independent loads (MLP_p1 = 9).
    // Rows 2p and 2p+1: A4/B4 indices 4p..4p+3. Per-warp access stays
    // contiguous (64B/thread stride within the warp's 16KB window).
    float4 a0 = __ldcs(&A4[p * 4 + 0]);
    float4 a1 = __ldcs(&A4[p * 4 + 1]);
    float4 a2 = __ldcs(&A4[p * 4 + 2]);
    float4 a3 = __ldcs(&A4[p * 4 + 3]);
    float4 b0 = __ldcs(&B4[p * 4 + 0]);
    float4 b1 = __ldcs(&B4[p * 4 + 1]);
    float4 b2 = __ldcs(&B4[p * 4 + 2]);
    float4 b3 = __ldcs(&B4[p * 4 + 3]);
    float2 c2 = __ldcs(&Cin2[p]);

    float4 s0, s1, s2, s3;
    float co0, co1;
    ripple8(a0, a1, b0, b1, c2.x, s0, s1, co0);
    ripple8(a2, a3, b2, b3, c2.y, s2, s3, co1);

    __stcs(&S4[p * 4 + 0], s0);
    __stcs(&S4[p * 4 + 1], s1);
    __stcs(&S4[p * 4 + 2], s2);
    __stcs(&S4[p * 4 + 3], s3);
    __stcs(&Cout2[p], make_float2(co0, co1));
}

extern "C" void kernel_launch(void* const* d_in, const int* in_sizes, int n_in,
                              void* d_out, int out_size) {
    const float* A   = (const float*)d_in[0];
    const float* B   = (const float*)d_in[1];
    const float* Cin = (const float*)d_in[2];

    int N = in_sizes[0] / 8;      // rows; N = 2^23 (even)
    int Npairs = N / 2;

    float* out   = (float*)d_out;
    float* cout_ = out + (size_t)N * 8;

    int threads = 256;
    int blocks  = (Npairs + threads - 1) / threads;
    adder8_kernel<<<blocks, threads>>>((const float4*)A, (const float4*)B,
                                       (const float2*)Cin,
                                       (float4*)out, (float2*)cout_, Npairs);
}